// round 8
// baseline (speedup 1.0000x reference)
#include <cuda_runtime.h>
#include <cuda_bf16.h>
#include <stdint.h>
#include <math.h>

// Problem constants
#define BB 16
#define TT 128
#define DD 8192           // C*H*W
#define FF 16             // NUM_FEAT
#define GG 4096           // NUM_FEAT*H*W
#define MM (BB*TT)        // 2048 rows

// ---------------- scratch (device globals; no allocs allowed) ----------------
__device__ float g_q[MM * FF];
__device__ float g_k[MM * FF];
__device__ float g_attn[BB * TT * TT];
__device__ float g_rs[MM];
__device__ __nv_bfloat16 g_yhi[(size_t)MM * DD];   // 32 MB, row-major [m][k]
__device__ __nv_bfloat16 g_ylo[(size_t)MM * DD];   // 32 MB
__device__ __nv_bfloat16 g_w3hi[(size_t)GG * DD];  // 64 MB, row-major [n][k]
__device__ __nv_bfloat16 g_w3lo[(size_t)GG * DD];  // 64 MB

// ======================= PTX helpers (compute_103-safe) ======================
__device__ __forceinline__ uint32_t smem_u32(const void* p) {
    uint32_t a;
    asm("{ .reg .u64 t; cvta.to.shared.u64 t, %1; cvt.u32.u64 %0, t; }" : "=r"(a) : "l"(p));
    return a;
}
__device__ __forceinline__ void cp_async16(uint32_t dst, const void* src) {
    asm volatile("cp.async.cg.shared.global [%0], [%1], 16;" :: "r"(dst), "l"(src) : "memory");
}
#define CP_COMMIT() asm volatile("cp.async.commit_group;" ::: "memory")
#define CP_WAIT2()  asm volatile("cp.async.wait_group 2;" ::: "memory")

__device__ __forceinline__ void ldsm4(uint32_t* r, uint32_t addr) {
    asm volatile("ldmatrix.sync.aligned.m8n8.x4.shared.b16 {%0,%1,%2,%3}, [%4];"
        : "=r"(r[0]), "=r"(r[1]), "=r"(r[2]), "=r"(r[3]) : "r"(addr));
}
__device__ __forceinline__ void mma16816(float* d, const uint32_t* a, uint32_t b0, uint32_t b1) {
    asm volatile("mma.sync.aligned.m16n8k16.row.col.f32.bf16.bf16.f32 "
        "{%0,%1,%2,%3}, {%4,%5,%6,%7}, {%8,%9}, {%0,%1,%2,%3};"
        : "+f"(d[0]), "+f"(d[1]), "+f"(d[2]), "+f"(d[3])
        : "r"(a[0]), "r"(a[1]), "r"(a[2]), "r"(a[3]), "r"(b0), "r"(b1));
}

// =============================================================================
// K1: q = x1 @ w1^T + b1 ; k = x2 @ w2^T + b2
// =============================================================================
__global__ __launch_bounds__(256) void k_qk(
    const float* __restrict__ x1, const float* __restrict__ x2,
    const float* __restrict__ w1, const float* __restrict__ b1,
    const float* __restrict__ w2, const float* __restrict__ b2)
{
    __shared__ float Xs1[16][132];
    __shared__ float Xs2[16][132];
    __shared__ float Ws1[16][132];
    __shared__ float Ws2[16][132];

    const int tid  = threadIdx.x;
    const int r    = tid >> 4;
    const int f    = tid & 15;
    const int row0 = blockIdx.x * 16;

    float accq = 0.f, acck = 0.f;
    for (int kc = 0; kc < DD; kc += 128) {
        #pragma unroll
        for (int i = 0; i < 2; ++i) {
            int lin = tid + i * 256;
            int row = lin >> 5;
            int col = (lin & 31) << 2;
            *(float4*)&Xs1[row][col] = *(const float4*)&x1[(size_t)(row0 + row) * DD + kc + col];
            *(float4*)&Xs2[row][col] = *(const float4*)&x2[(size_t)(row0 + row) * DD + kc + col];
            *(float4*)&Ws1[row][col] = *(const float4*)&w1[(size_t)row * DD + kc + col];
            *(float4*)&Ws2[row][col] = *(const float4*)&w2[(size_t)row * DD + kc + col];
        }
        __syncthreads();
        #pragma unroll 8
        for (int kk = 0; kk < 128; ++kk) {
            accq += Xs1[r][kk] * Ws1[f][kk];
            acck += Xs2[r][kk] * Ws2[f][kk];
        }
        __syncthreads();
    }
    g_q[(row0 + r) * FF + f] = accq + b1[f];
    g_k[(row0 + r) * FF + f] = acck + b2[f];
}

// =============================================================================
// K2: scores + softmax over t (axis=1) + rowsums
// =============================================================================
__global__ __launch_bounds__(128) void k_scores_softmax()
{
    __shared__ float qs[TT][17];
    __shared__ float redp[4][TT];

    const int b = blockIdx.x;
    const int s = threadIdx.x;
    const int lane = s & 31, wid = s >> 5;

    #pragma unroll
    for (int i = 0; i < 16; ++i) {
        int lin = s + i * 128;
        int t = lin >> 4, f = lin & 15;
        qs[t][f] = g_q[(b * TT + t) * FF + f];
    }
    float kr[FF];
    #pragma unroll
    for (int j = 0; j < FF; ++j) kr[j] = g_k[(b * TT + s) * FF + j];
    __syncthreads();

    float m = -1e30f, l = 0.f;
    for (int t = 0; t < TT; ++t) {
        float sc = 0.f;
        #pragma unroll
        for (int j = 0; j < FF; ++j) sc += qs[t][j] * kr[j];
        float nm = fmaxf(m, sc);
        l = l * expf(m - nm) + expf(sc - nm);
        m = nm;
    }
    float inv = 1.f / l;

    for (int t = 0; t < TT; ++t) {
        float sc = 0.f;
        #pragma unroll
        for (int j = 0; j < FF; ++j) sc += qs[t][j] * kr[j];
        float a = expf(sc - m) * inv;
        g_attn[(b * TT + t) * TT + s] = a;

        float v = a;
        #pragma unroll
        for (int off = 16; off > 0; off >>= 1)
            v += __shfl_down_sync(0xffffffffu, v, off);
        if (lane == 0) redp[wid][t] = v;
    }
    __syncthreads();
    if (s < TT)
        g_rs[b * TT + s] = redp[0][s] + redp[1][s] + redp[2][s] + redp[3][s];
}

// =============================================================================
// K3: y[b,t,d] = sum_s attn[b,t,s] * x1[b,s,d] -> bf16 hi/lo, s unrolled x4
// =============================================================================
__global__ __launch_bounds__(512) void k_y(const float* __restrict__ x1)
{
    __shared__ float AsT[TT][68];

    const int tid = threadIdx.x;
    const int b   = blockIdx.z;
    const int t0  = blockIdx.y * 64;
    const int col = blockIdx.x * 512 + tid;

    #pragma unroll
    for (int i = 0; i < 16; ++i) {
        int lin = tid + i * 512;
        int s = lin & 127, t = lin >> 7;
        AsT[s][t] = g_attn[(b * TT + t0 + t) * TT + s];
    }
    __syncthreads();

    float acc[64];
    #pragma unroll
    for (int t = 0; t < 64; ++t) acc[t] = 0.f;

    const float* xp = x1 + (size_t)b * TT * DD + col;
    for (int s = 0; s < TT; s += 4) {
        float xv0 = xp[(size_t)(s + 0) * DD];
        float xv1 = xp[(size_t)(s + 1) * DD];
        float xv2 = xp[(size_t)(s + 2) * DD];
        float xv3 = xp[(size_t)(s + 3) * DD];
        #pragma unroll
        for (int u = 0; u < 4; ++u) {
            float xv = (u == 0) ? xv0 : (u == 1) ? xv1 : (u == 2) ? xv2 : xv3;
            const float4* ar = (const float4*)&AsT[s + u][0];
            #pragma unroll
            for (int q4 = 0; q4 < 16; ++q4) {
                float4 a = ar[q4];
                acc[q4 * 4 + 0] += a.x * xv;
                acc[q4 * 4 + 1] += a.y * xv;
                acc[q4 * 4 + 2] += a.z * xv;
                acc[q4 * 4 + 3] += a.w * xv;
            }
        }
    }
    #pragma unroll
    for (int t = 0; t < 64; ++t) {
        float v = acc[t];
        __nv_bfloat16 h = __float2bfloat16(v);
        __nv_bfloat16 lo = __float2bfloat16(v - __bfloat162float(h));
        size_t off = (size_t)(b * TT + t0 + t) * DD + col;
        g_yhi[off] = h;
        g_ylo[off] = lo;
    }
}

// =============================================================================
// K_split_w3: fp32 [G][D] -> bf16 hi/lo row-major (streaming)
// =============================================================================
__global__ __launch_bounds__(256) void k_split_w3(const float* __restrict__ src)
{
    size_t i4 = ((size_t)blockIdx.x * 256 + threadIdx.x);
    float4 v = *(const float4*)&src[i4 * 4];
    __nv_bfloat16 h0 = __float2bfloat16(v.x), h1 = __float2bfloat16(v.y);
    __nv_bfloat16 h2 = __float2bfloat16(v.z), h3 = __float2bfloat16(v.w);
    __nv_bfloat162 hp0; hp0.x = h0; hp0.y = h1;
    __nv_bfloat162 hp1; hp1.x = h2; hp1.y = h3;
    __nv_bfloat162 lp0, lp1;
    lp0.x = __float2bfloat16(v.x - __bfloat162float(h0));
    lp0.y = __float2bfloat16(v.y - __bfloat162float(h1));
    lp1.x = __float2bfloat16(v.z - __bfloat162float(h2));
    lp1.y = __float2bfloat16(v.w - __bfloat162float(h3));
    uint2 hu, lu;
    hu.x = *(uint32_t*)&hp0; hu.y = *(uint32_t*)&hp1;
    lu.x = *(uint32_t*)&lp0; lu.y = *(uint32_t*)&lp1;
    *(uint2*)&g_w3hi[i4 * 4] = hu;
    *(uint2*)&g_w3lo[i4 * 4] = lu;
}

// =============================================================================
// K4: out[m,g] = sum_k y[m,k] w3[g,k] + rs[m] b3[g]
// bf16 hi/lo 3-product HMMA. Block tile 256x128, BK=32, 512 threads,
// 16 warps (4m x 4n), warp tile 64x32 -> acc=64 regs.
// Two-pass product schedule: pass1 Ah*(Bh,Bl), pass2 Al*Bh reusing A frag regs
// -> peak live frags 24 (vs 48), no spills at the 128-reg cap.
// 4-stage pipeline (192KB smem), wait_group 2 -> 3 stages of load overlap.
// =============================================================================
#define STAGE_BYTES 49152
#define NSTG 4
#define SMEM_K4 (NSTG * STAGE_BYTES)
#define OFF_AL 16384
#define OFF_BH 32768
#define OFF_BL 40960

__global__ __launch_bounds__(512) void k_out_tc(
    const float* __restrict__ b3, float* __restrict__ out)
{
    extern __shared__ char smem[];
    const uint32_t sb = smem_u32(smem);
    const int tid  = threadIdx.x;
    const int lane = tid & 31;
    const int wid  = tid >> 5;
    const int wm   = wid & 3;          // warp m index (0..3), 64 rows each
    const int wn   = wid >> 2;         // warp n index (0..3), 32 cols each
    const int rb   = blockIdx.x;       // M tile (0..7)   -> 256 rows
    const int nb   = blockIdx.y;       // N tile (0..31)  -> 128 cols

    const __nv_bfloat16* aH = g_yhi  + (size_t)rb * 256 * DD;
    const __nv_bfloat16* aL = g_ylo  + (size_t)rb * 256 * DD;
    const __nv_bfloat16* bH = g_w3hi + (size_t)nb * 128 * DD;
    const __nv_bfloat16* bL = g_w3lo + (size_t)nb * 128 * DD;

    // loader: 6 x 16B chunks per thread per stage (A: 4, B: 2)
    auto issue_stage = [&](int kt, int stage) {
        const uint32_t sbase = sb + stage * STAGE_BYTES;
        #pragma unroll
        for (int i = 0; i < 4; ++i) {                 // A hi/lo: 2048 chunks
            const int id  = i * 512 + tid;
            const int arr = id >> 10;                 // 0=Ah 1=Al
            const int w   = id & 1023;
            const int r   = w >> 2;                   // 0..255
            const int c   = w & 3;
            uint32_t dst = sbase + arr * OFF_AL + r * 64 + ((c ^ ((r >> 1) & 3)) << 4);
            const __nv_bfloat16* base = arr ? aL : aH;
            cp_async16(dst, base + (size_t)r * DD + kt * 32 + c * 8);
        }
        #pragma unroll
        for (int i = 0; i < 2; ++i) {                 // B hi/lo: 1024 chunks
            const int id  = i * 512 + tid;
            const int arr = id >> 9;                  // 0=Bh 1=Bl
            const int w   = id & 511;
            const int r   = w >> 2;                   // 0..127
            const int c   = w & 3;
            uint32_t dst = sbase + OFF_BH + arr * 8192 + r * 64 + ((c ^ ((r >> 1) & 3)) << 4);
            const __nv_bfloat16* base = arr ? bL : bH;
            cp_async16(dst, base + (size_t)r * DD + kt * 32 + c * 8);
        }
    };

    float acc[4][4][4];                               // [mf][n8][frag]
    #pragma unroll
    for (int a = 0; a < 4; ++a)
        #pragma unroll
        for (int b = 0; b < 4; ++b)
            #pragma unroll
            for (int c = 0; c < 4; ++c) acc[a][b][c] = 0.f;

    const int r_lane = (lane & 7) + ((lane >> 3) & 1) * 8;
    const int c_lane = lane >> 4;                     // 0 or 1

    int rA64[4], rAx[4], rB64[2], rBx[2];
    #pragma unroll
    for (int f = 0; f < 4; ++f) {
        int ra = wm * 64 + f * 16 + r_lane;
        rA64[f] = ra * 64; rAx[f] = (ra >> 1) & 3;
    }
    #pragma unroll
    for (int f = 0; f < 2; ++f) {
        int rn = wn * 32 + f * 16 + r_lane;
        rB64[f] = rn * 64; rBx[f] = (rn >> 1) & 3;
    }

    issue_stage(0, 0); CP_COMMIT();
    issue_stage(1, 1); CP_COMMIT();
    issue_stage(2, 2); CP_COMMIT();

    const int KT = DD / 32;                           // 256
    for (int kt = 0; kt < KT; ++kt) {
        CP_WAIT2();
        __syncthreads();

        const uint32_t sbase = sb + (kt & (NSTG - 1)) * STAGE_BYTES;
        #pragma unroll
        for (int ks = 0; ks < 2; ++ks) {
            const int cbase = 2 * ks + c_lane;
            uint32_t af[4][4];

            // ---- pass 1: A_hi x (B_hi, B_lo) ----
            #pragma unroll
            for (int mf = 0; mf < 4; ++mf)
                ldsm4(af[mf], sbase + rA64[mf] + ((cbase ^ rAx[mf]) << 4));
            #pragma unroll
            for (int nf2 = 0; nf2 < 2; ++nf2) {
                uint32_t off = rB64[nf2] + ((cbase ^ rBx[nf2]) << 4);
                uint32_t b_hi[4], b_lo[4];
                ldsm4(b_hi, sbase + OFF_BH + off);
                ldsm4(b_lo, sbase + OFF_BL + off);
                #pragma unroll
                for (int mf = 0; mf < 4; ++mf) {
                    #pragma unroll
                    for (int s = 0; s < 2; ++s) {
                        float* d = acc[mf][nf2 * 2 + s];
                        mma16816(d, af[mf], b_hi[s], b_hi[s + 2]);
                        mma16816(d, af[mf], b_lo[s], b_lo[s + 2]);
                    }
                }
            }

            // ---- pass 2: A_lo x B_hi (reuse af registers) ----
            #pragma unroll
            for (int mf = 0; mf < 4; ++mf)
                ldsm4(af[mf], sbase + OFF_AL + rA64[mf] + ((cbase ^ rAx[mf]) << 4));
            #pragma unroll
            for (int nf2 = 0; nf2 < 2; ++nf2) {
                uint32_t off = rB64[nf2] + ((cbase ^ rBx[nf2]) << 4);
                uint32_t b_hi[4];
                ldsm4(b_hi, sbase + OFF_BH + off);
                #pragma unroll
                for (int mf = 0; mf < 4; ++mf) {
                    #pragma unroll
                    for (int s = 0; s < 2; ++s)
                        mma16816(acc[mf][nf2 * 2 + s], af[mf], b_hi[s], b_hi[s + 2]);
                }
            }
        }
        __syncthreads();
        if (kt + 3 < KT) { issue_stage(kt + 3, (kt + 3) & (NSTG - 1)); }
        CP_COMMIT();
    }

    // ---- epilogue: out = acc + rs[m]*b3[g] ----
    const int r_ep  = lane >> 2;
    const int cpair = (lane & 3) * 2;

    float rsv[4][2];
    #pragma unroll
    for (int mf = 0; mf < 4; ++mf) {
        int row = rb * 256 + wm * 64 + mf * 16 + r_ep;
        rsv[mf][0] = g_rs[row];
        rsv[mf][1] = g_rs[row + 8];
    }
    float b3v[4][2];
    #pragma unroll
    for (int nf = 0; nf < 4; ++nf) {
        int colg = nb * 128 + wn * 32 + nf * 8 + cpair;
        b3v[nf][0] = b3[colg];
        b3v[nf][1] = b3[colg + 1];
    }

    #pragma unroll
    for (int mf = 0; mf < 4; ++mf) {
        #pragma unroll
        for (int nf = 0; nf < 4; ++nf) {
            int row  = rb * 256 + wm * 64 + mf * 16 + r_ep;
            int colg = nb * 128 + wn * 32 + nf * 8 + cpair;
            float2 v0, v1;
            v0.x = acc[mf][nf][0] + rsv[mf][0] * b3v[nf][0];
            v0.y = acc[mf][nf][1] + rsv[mf][0] * b3v[nf][1];
            v1.x = acc[mf][nf][2] + rsv[mf][1] * b3v[nf][0];
            v1.y = acc[mf][nf][3] + rsv[mf][1] * b3v[nf][1];
            *(float2*)&out[(size_t)row * GG + colg]       = v0;
            *(float2*)&out[(size_t)(row + 8) * GG + colg] = v1;
        }
    }
}

// =============================================================================
extern "C" void kernel_launch(void* const* d_in, const int* in_sizes, int n_in,
                              void* d_out, int out_size)
{
    const float* x1 = (const float*)d_in[0];
    const float* x2 = (const float*)d_in[1];
    const float* w1 = (const float*)d_in[2];
    const float* b1 = (const float*)d_in[3];
    const float* w2 = (const float*)d_in[4];
    const float* b2 = (const float*)d_in[5];
    const float* w3 = (const float*)d_in[6];
    const float* b3 = (const float*)d_in[7];
    float* out = (float*)d_out;

    cudaFuncSetAttribute(k_out_tc, cudaFuncAttributeMaxDynamicSharedMemorySize, SMEM_K4);

    k_split_w3<<<(size_t)GG * DD / (256 * 4), 256>>>(w3);
    k_qk<<<MM / 16, 256>>>(x1, x2, w1, b1, w2, b2);
    k_scores_softmax<<<BB, 128>>>();
    k_y<<<dim3(DD / 512, TT / 64, BB), 512>>>(x1);
    k_out_tc<<<dim3(MM / 256, GG / 128), 512, SMEM_K4>>>(b3, out);
}

// round 9
// speedup vs baseline: 1.9240x; 1.9240x over previous
#include <cuda_runtime.h>
#include <cuda_bf16.h>
#include <cuda_fp16.h>
#include <stdint.h>
#include <math.h>

// Problem constants
#define BB 16
#define TT 128
#define DD 8192           // C*H*W
#define FF 16             // NUM_FEAT
#define GG 4096           // NUM_FEAT*H*W
#define MM (BB*TT)        // 2048 rows

// ---------------- scratch (device globals; no allocs allowed) ----------------
__device__ float g_q[MM * FF];
__device__ float g_k[MM * FF];
__device__ float g_attn[BB * TT * TT];
__device__ float g_rs[MM];
__device__ __half g_yh[(size_t)MM * DD];    // 32 MB, row-major [m][k], fp16
__device__ __half g_w3h[(size_t)GG * DD];   // 64 MB, row-major [n][k], fp16

// ======================= PTX helpers (compute_103-safe) ======================
__device__ __forceinline__ uint32_t smem_u32(const void* p) {
    uint32_t a;
    asm("{ .reg .u64 t; cvta.to.shared.u64 t, %1; cvt.u32.u64 %0, t; }" : "=r"(a) : "l"(p));
    return a;
}
__device__ __forceinline__ void cp_async16(uint32_t dst, const void* src) {
    asm volatile("cp.async.cg.shared.global [%0], [%1], 16;" :: "r"(dst), "l"(src) : "memory");
}
#define CP_COMMIT() asm volatile("cp.async.commit_group;" ::: "memory")
#define CP_WAIT2()  asm volatile("cp.async.wait_group 2;" ::: "memory")

__device__ __forceinline__ void ldsm4(uint32_t* r, uint32_t addr) {
    asm volatile("ldmatrix.sync.aligned.m8n8.x4.shared.b16 {%0,%1,%2,%3}, [%4];"
        : "=r"(r[0]), "=r"(r[1]), "=r"(r[2]), "=r"(r[3]) : "r"(addr));
}
__device__ __forceinline__ void mma16816h(float* d, const uint32_t* a, uint32_t b0, uint32_t b1) {
    asm volatile("mma.sync.aligned.m16n8k16.row.col.f32.f16.f16.f32 "
        "{%0,%1,%2,%3}, {%4,%5,%6,%7}, {%8,%9}, {%0,%1,%2,%3};"
        : "+f"(d[0]), "+f"(d[1]), "+f"(d[2]), "+f"(d[3])
        : "r"(a[0]), "r"(a[1]), "r"(a[2]), "r"(a[3]), "r"(b0), "r"(b1));
}

// =============================================================================
// K1: q = x1 @ w1^T + b1 ; k = x2 @ w2^T + b2
// =============================================================================
__global__ __launch_bounds__(256) void k_qk(
    const float* __restrict__ x1, const float* __restrict__ x2,
    const float* __restrict__ w1, const float* __restrict__ b1,
    const float* __restrict__ w2, const float* __restrict__ b2)
{
    __shared__ float Xs1[16][132];
    __shared__ float Xs2[16][132];
    __shared__ float Ws1[16][132];
    __shared__ float Ws2[16][132];

    const int tid  = threadIdx.x;
    const int r    = tid >> 4;
    const int f    = tid & 15;
    const int row0 = blockIdx.x * 16;

    float accq = 0.f, acck = 0.f;
    for (int kc = 0; kc < DD; kc += 128) {
        #pragma unroll
        for (int i = 0; i < 2; ++i) {
            int lin = tid + i * 256;
            int row = lin >> 5;
            int col = (lin & 31) << 2;
            *(float4*)&Xs1[row][col] = *(const float4*)&x1[(size_t)(row0 + row) * DD + kc + col];
            *(float4*)&Xs2[row][col] = *(const float4*)&x2[(size_t)(row0 + row) * DD + kc + col];
            *(float4*)&Ws1[row][col] = *(const float4*)&w1[(size_t)row * DD + kc + col];
            *(float4*)&Ws2[row][col] = *(const float4*)&w2[(size_t)row * DD + kc + col];
        }
        __syncthreads();
        #pragma unroll 8
        for (int kk = 0; kk < 128; ++kk) {
            accq += Xs1[r][kk] * Ws1[f][kk];
            acck += Xs2[r][kk] * Ws2[f][kk];
        }
        __syncthreads();
    }
    g_q[(row0 + r) * FF + f] = accq + b1[f];
    g_k[(row0 + r) * FF + f] = acck + b2[f];
}

// =============================================================================
// K2: scores + softmax over t (axis=1) + rowsums
// =============================================================================
__global__ __launch_bounds__(128) void k_scores_softmax()
{
    __shared__ float qs[TT][17];
    __shared__ float redp[4][TT];

    const int b = blockIdx.x;
    const int s = threadIdx.x;
    const int lane = s & 31, wid = s >> 5;

    #pragma unroll
    for (int i = 0; i < 16; ++i) {
        int lin = s + i * 128;
        int t = lin >> 4, f = lin & 15;
        qs[t][f] = g_q[(b * TT + t) * FF + f];
    }
    float kr[FF];
    #pragma unroll
    for (int j = 0; j < FF; ++j) kr[j] = g_k[(b * TT + s) * FF + j];
    __syncthreads();

    float m = -1e30f, l = 0.f;
    for (int t = 0; t < TT; ++t) {
        float sc = 0.f;
        #pragma unroll
        for (int j = 0; j < FF; ++j) sc += qs[t][j] * kr[j];
        float nm = fmaxf(m, sc);
        l = l * expf(m - nm) + expf(sc - nm);
        m = nm;
    }
    float inv = 1.f / l;

    for (int t = 0; t < TT; ++t) {
        float sc = 0.f;
        #pragma unroll
        for (int j = 0; j < FF; ++j) sc += qs[t][j] * kr[j];
        float a = expf(sc - m) * inv;
        g_attn[(b * TT + t) * TT + s] = a;

        float v = a;
        #pragma unroll
        for (int off = 16; off > 0; off >>= 1)
            v += __shfl_down_sync(0xffffffffu, v, off);
        if (lane == 0) redp[wid][t] = v;
    }
    __syncthreads();
    if (s < TT)
        g_rs[b * TT + s] = redp[0][s] + redp[1][s] + redp[2][s] + redp[3][s];
}

// =============================================================================
// K3: y[b,t,d] = sum_s attn[b,t,s] * x1[b,s,d] -> fp16, s unrolled x4
// =============================================================================
__global__ __launch_bounds__(512) void k_y(const float* __restrict__ x1)
{
    __shared__ float AsT[TT][68];

    const int tid = threadIdx.x;
    const int b   = blockIdx.z;
    const int t0  = blockIdx.y * 64;
    const int col = blockIdx.x * 512 + tid;

    #pragma unroll
    for (int i = 0; i < 16; ++i) {
        int lin = tid + i * 512;
        int s = lin & 127, t = lin >> 7;
        AsT[s][t] = g_attn[(b * TT + t0 + t) * TT + s];
    }
    __syncthreads();

    float acc[64];
    #pragma unroll
    for (int t = 0; t < 64; ++t) acc[t] = 0.f;

    const float* xp = x1 + (size_t)b * TT * DD + col;
    for (int s = 0; s < TT; s += 4) {
        float xv0 = xp[(size_t)(s + 0) * DD];
        float xv1 = xp[(size_t)(s + 1) * DD];
        float xv2 = xp[(size_t)(s + 2) * DD];
        float xv3 = xp[(size_t)(s + 3) * DD];
        #pragma unroll
        for (int u = 0; u < 4; ++u) {
            float xv = (u == 0) ? xv0 : (u == 1) ? xv1 : (u == 2) ? xv2 : xv3;
            const float4* ar = (const float4*)&AsT[s + u][0];
            #pragma unroll
            for (int q4 = 0; q4 < 16; ++q4) {
                float4 a = ar[q4];
                acc[q4 * 4 + 0] += a.x * xv;
                acc[q4 * 4 + 1] += a.y * xv;
                acc[q4 * 4 + 2] += a.z * xv;
                acc[q4 * 4 + 3] += a.w * xv;
            }
        }
    }
    #pragma unroll
    for (int t = 0; t < 64; ++t) {
        size_t off = (size_t)(b * TT + t0 + t) * DD + col;
        g_yh[off] = __float2half_rn(acc[t]);
    }
}

// =============================================================================
// K_split_w3: fp32 [G][D] -> fp16 row-major (streaming)
// =============================================================================
__global__ __launch_bounds__(256) void k_split_w3(const float* __restrict__ src)
{
    size_t i4 = ((size_t)blockIdx.x * 256 + threadIdx.x);
    float4 v = *(const float4*)&src[i4 * 4];
    __half2 h0; h0.x = __float2half_rn(v.x); h0.y = __float2half_rn(v.y);
    __half2 h1; h1.x = __float2half_rn(v.z); h1.y = __float2half_rn(v.w);
    uint2 hu;
    hu.x = *(uint32_t*)&h0; hu.y = *(uint32_t*)&h1;
    *(uint2*)&g_w3h[i4 * 4] = hu;
}

// =============================================================================
// K4: out[m,g] = sum_k y[m,k] w3[g,k] + rs[m] b3[g]
// Single-product fp16 HMMA. Block tile 256x128, BK=32, 512 threads,
// 16 warps (4m x 4n), warp tile 64x32 -> acc=64 regs, 32 MMAs/warp/kt.
// Stage: A 16K | B 8K = 24KB, 4 stages = 96KB, wait_group 2.
// Smem rows 64B, chunk swizzle c ^= (r>>1)&3 (ldsm + cp.async conflict-free).
// =============================================================================
#define STAGE_BYTES 24576
#define NSTG 4
#define SMEM_K4 (NSTG * STAGE_BYTES)
#define OFF_B 16384

__global__ __launch_bounds__(512) void k_out_tc(
    const float* __restrict__ b3, float* __restrict__ out)
{
    extern __shared__ char smem[];
    const uint32_t sb = smem_u32(smem);
    const int tid  = threadIdx.x;
    const int lane = tid & 31;
    const int wid  = tid >> 5;
    const int wm   = wid & 3;          // warp m index (0..3), 64 rows each
    const int wn   = wid >> 2;         // warp n index (0..3), 32 cols each
    const int rb   = blockIdx.x;       // M tile (0..7)   -> 256 rows
    const int nb   = blockIdx.y;       // N tile (0..31)  -> 128 cols

    const __half* aP = g_yh  + (size_t)rb * 256 * DD;
    const __half* bP = g_w3h + (size_t)nb * 128 * DD;

    // loader: 3 x 16B chunks per thread per stage (A: 2, B: 1)
    auto issue_stage = [&](int kt, int stage) {
        const uint32_t sbase = sb + stage * STAGE_BYTES;
        #pragma unroll
        for (int i = 0; i < 2; ++i) {                 // A: 1024 chunks
            const int id = i * 512 + tid;
            const int r  = id >> 2;                   // 0..255
            const int c  = id & 3;
            uint32_t dst = sbase + r * 64 + ((c ^ ((r >> 1) & 3)) << 4);
            cp_async16(dst, aP + (size_t)r * DD + kt * 32 + c * 8);
        }
        {                                             // B: 512 chunks
            const int r = tid >> 2;                   // 0..127
            const int c = tid & 3;
            uint32_t dst = sbase + OFF_B + r * 64 + ((c ^ ((r >> 1) & 3)) << 4);
            cp_async16(dst, bP + (size_t)r * DD + kt * 32 + c * 8);
        }
    };

    float acc[4][4][4];                               // [mf][n8][frag]
    #pragma unroll
    for (int a = 0; a < 4; ++a)
        #pragma unroll
        for (int b = 0; b < 4; ++b)
            #pragma unroll
            for (int c = 0; c < 4; ++c) acc[a][b][c] = 0.f;

    const int r_lane = (lane & 7) + ((lane >> 3) & 1) * 8;
    const int c_lane = lane >> 4;                     // 0 or 1

    int rA64[4], rAx[4], rB64[2], rBx[2];
    #pragma unroll
    for (int f = 0; f < 4; ++f) {
        int ra = wm * 64 + f * 16 + r_lane;
        rA64[f] = ra * 64; rAx[f] = (ra >> 1) & 3;
    }
    #pragma unroll
    for (int f = 0; f < 2; ++f) {
        int rn = wn * 32 + f * 16 + r_lane;
        rB64[f] = rn * 64; rBx[f] = (rn >> 1) & 3;
    }

    issue_stage(0, 0); CP_COMMIT();
    issue_stage(1, 1); CP_COMMIT();
    issue_stage(2, 2); CP_COMMIT();

    const int KT = DD / 32;                           // 256
    for (int kt = 0; kt < KT; ++kt) {
        CP_WAIT2();
        __syncthreads();

        const uint32_t sbase = sb + (kt & (NSTG - 1)) * STAGE_BYTES;
        #pragma unroll
        for (int ks = 0; ks < 2; ++ks) {
            const int cbase = 2 * ks + c_lane;
            uint32_t af[4][4];
            #pragma unroll
            for (int mf = 0; mf < 4; ++mf)
                ldsm4(af[mf], sbase + rA64[mf] + ((cbase ^ rAx[mf]) << 4));
            #pragma unroll
            for (int nf2 = 0; nf2 < 2; ++nf2) {
                uint32_t bf[4];
                ldsm4(bf, sbase + OFF_B + rB64[nf2] + ((cbase ^ rBx[nf2]) << 4));
                #pragma unroll
                for (int mf = 0; mf < 4; ++mf) {
                    #pragma unroll
                    for (int s = 0; s < 2; ++s)
                        mma16816h(acc[mf][nf2 * 2 + s], af[mf], bf[s], bf[s + 2]);
                }
            }
        }
        __syncthreads();
        if (kt + 3 < KT) { issue_stage(kt + 3, (kt + 3) & (NSTG - 1)); }
        CP_COMMIT();
    }

    // ---- epilogue: out = acc + rs[m]*b3[g] ----
    const int r_ep  = lane >> 2;
    const int cpair = (lane & 3) * 2;

    float rsv[4][2];
    #pragma unroll
    for (int mf = 0; mf < 4; ++mf) {
        int row = rb * 256 + wm * 64 + mf * 16 + r_ep;
        rsv[mf][0] = g_rs[row];
        rsv[mf][1] = g_rs[row + 8];
    }
    float b3v[4][2];
    #pragma unroll
    for (int nf = 0; nf < 4; ++nf) {
        int colg = nb * 128 + wn * 32 + nf * 8 + cpair;
        b3v[nf][0] = b3[colg];
        b3v[nf][1] = b3[colg + 1];
    }

    #pragma unroll
    for (int mf = 0; mf < 4; ++mf) {
        #pragma unroll
        for (int nf = 0; nf < 4; ++nf) {
            int row  = rb * 256 + wm * 64 + mf * 16 + r_ep;
            int colg = nb * 128 + wn * 32 + nf * 8 + cpair;
            float2 v0, v1;
            v0.x = acc[mf][nf][0] + rsv[mf][0] * b3v[nf][0];
            v0.y = acc[mf][nf][1] + rsv[mf][0] * b3v[nf][1];
            v1.x = acc[mf][nf][2] + rsv[mf][1] * b3v[nf][0];
            v1.y = acc[mf][nf][3] + rsv[mf][1] * b3v[nf][1];
            *(float2*)&out[(size_t)row * GG + colg]       = v0;
            *(float2*)&out[(size_t)(row + 8) * GG + colg] = v1;
        }
    }
}

// =============================================================================
extern "C" void kernel_launch(void* const* d_in, const int* in_sizes, int n_in,
                              void* d_out, int out_size)
{
    const float* x1 = (const float*)d_in[0];
    const float* x2 = (const float*)d_in[1];
    const float* w1 = (const float*)d_in[2];
    const float* b1 = (const float*)d_in[3];
    const float* w2 = (const float*)d_in[4];
    const float* b2 = (const float*)d_in[5];
    const float* w3 = (const float*)d_in[6];
    const float* b3 = (const float*)d_in[7];
    float* out = (float*)d_out;

    cudaFuncSetAttribute(k_out_tc, cudaFuncAttributeMaxDynamicSharedMemorySize, SMEM_K4);

    k_split_w3<<<(size_t)GG * DD / (256 * 4), 256>>>(w3);
    k_qk<<<MM / 16, 256>>>(x1, x2, w1, b1, w2, b2);
    k_scores_softmax<<<BB, 128>>>();
    k_y<<<dim3(DD / 512, TT / 64, BB), 512>>>(x1);
    k_out_tc<<<dim3(MM / 256, GG / 128), 512, SMEM_K4>>>(b3, out);
}

// round 10
// speedup vs baseline: 2.2435x; 1.1661x over previous
#include <cuda_runtime.h>
#include <cuda_bf16.h>
#include <cuda_fp16.h>
#include <stdint.h>
#include <math.h>

// Problem constants
#define BB 16
#define TT 128
#define DD 8192           // C*H*W
#define FF 16             // NUM_FEAT
#define GG 4096           // NUM_FEAT*H*W
#define MM (BB*TT)        // 2048 rows

// ---------------- scratch (device globals; no allocs allowed) ----------------
__device__ float g_q[MM * FF];
__device__ float g_k[MM * FF];
__device__ __half g_attnh[BB * TT * TT];    // attn fp16 [b][t][s], 512 KB
__device__ float g_rs[MM];
__device__ __half g_yh[(size_t)MM * DD];    // 32 MB, row-major [m][k], fp16
__device__ __half g_w3h[(size_t)GG * DD];   // 64 MB, row-major [n][k], fp16

// ======================= PTX helpers (compute_103-safe) ======================
__device__ __forceinline__ uint32_t smem_u32(const void* p) {
    uint32_t a;
    asm("{ .reg .u64 t; cvta.to.shared.u64 t, %1; cvt.u32.u64 %0, t; }" : "=r"(a) : "l"(p));
    return a;
}
__device__ __forceinline__ void cp_async16(uint32_t dst, const void* src) {
    asm volatile("cp.async.cg.shared.global [%0], [%1], 16;" :: "r"(dst), "l"(src) : "memory");
}
#define CP_COMMIT() asm volatile("cp.async.commit_group;" ::: "memory")
#define CP_WAIT2()  asm volatile("cp.async.wait_group 2;" ::: "memory")
#define CP_WAIT0()  asm volatile("cp.async.wait_group 0;" ::: "memory")

__device__ __forceinline__ void ldsm4(uint32_t* r, uint32_t addr) {
    asm volatile("ldmatrix.sync.aligned.m8n8.x4.shared.b16 {%0,%1,%2,%3}, [%4];"
        : "=r"(r[0]), "=r"(r[1]), "=r"(r[2]), "=r"(r[3]) : "r"(addr));
}
__device__ __forceinline__ void ldsm4t(uint32_t* r, uint32_t addr) {
    asm volatile("ldmatrix.sync.aligned.m8n8.x4.trans.shared.b16 {%0,%1,%2,%3}, [%4];"
        : "=r"(r[0]), "=r"(r[1]), "=r"(r[2]), "=r"(r[3]) : "r"(addr));
}
__device__ __forceinline__ void mma16816h(float* d, const uint32_t* a, uint32_t b0, uint32_t b1) {
    asm volatile("mma.sync.aligned.m16n8k16.row.col.f32.f16.f16.f32 "
        "{%0,%1,%2,%3}, {%4,%5,%6,%7}, {%8,%9}, {%0,%1,%2,%3};"
        : "+f"(d[0]), "+f"(d[1]), "+f"(d[2]), "+f"(d[3])
        : "r"(a[0]), "r"(a[1]), "r"(a[2]), "r"(a[3]), "r"(b0), "r"(b1));
}

// =============================================================================
// K1: q = x1 @ w1^T + b1 ; k = x2 @ w2^T + b2  (unchanged)
// =============================================================================
__global__ __launch_bounds__(256) void k_qk(
    const float* __restrict__ x1, const float* __restrict__ x2,
    const float* __restrict__ w1, const float* __restrict__ b1,
    const float* __restrict__ w2, const float* __restrict__ b2)
{
    __shared__ float Xs1[16][132];
    __shared__ float Xs2[16][132];
    __shared__ float Ws1[16][132];
    __shared__ float Ws2[16][132];

    const int tid  = threadIdx.x;
    const int r    = tid >> 4;
    const int f    = tid & 15;
    const int row0 = blockIdx.x * 16;

    float accq = 0.f, acck = 0.f;
    for (int kc = 0; kc < DD; kc += 128) {
        #pragma unroll
        for (int i = 0; i < 2; ++i) {
            int lin = tid + i * 256;
            int row = lin >> 5;
            int col = (lin & 31) << 2;
            *(float4*)&Xs1[row][col] = *(const float4*)&x1[(size_t)(row0 + row) * DD + kc + col];
            *(float4*)&Xs2[row][col] = *(const float4*)&x2[(size_t)(row0 + row) * DD + kc + col];
            *(float4*)&Ws1[row][col] = *(const float4*)&w1[(size_t)row * DD + kc + col];
            *(float4*)&Ws2[row][col] = *(const float4*)&w2[(size_t)row * DD + kc + col];
        }
        __syncthreads();
        #pragma unroll 8
        for (int kk = 0; kk < 128; ++kk) {
            accq += Xs1[r][kk] * Ws1[f][kk];
            acck += Xs2[r][kk] * Ws2[f][kk];
        }
        __syncthreads();
    }
    g_q[(row0 + r) * FF + f] = accq + b1[f];
    g_k[(row0 + r) * FF + f] = acck + b2[f];
}

// =============================================================================
// K2: scores + softmax over t (axis=1) + rowsums; attn stored as fp16
// =============================================================================
__global__ __launch_bounds__(128) void k_scores_softmax()
{
    __shared__ float qs[TT][17];
    __shared__ float redp[4][TT];

    const int b = blockIdx.x;
    const int s = threadIdx.x;
    const int lane = s & 31, wid = s >> 5;

    #pragma unroll
    for (int i = 0; i < 16; ++i) {
        int lin = s + i * 128;
        int t = lin >> 4, f = lin & 15;
        qs[t][f] = g_q[(b * TT + t) * FF + f];
    }
    float kr[FF];
    #pragma unroll
    for (int j = 0; j < FF; ++j) kr[j] = g_k[(b * TT + s) * FF + j];
    __syncthreads();

    float m = -1e30f, l = 0.f;
    for (int t = 0; t < TT; ++t) {
        float sc = 0.f;
        #pragma unroll
        for (int j = 0; j < FF; ++j) sc += qs[t][j] * kr[j];
        float nm = fmaxf(m, sc);
        l = l * expf(m - nm) + expf(sc - nm);
        m = nm;
    }
    float inv = 1.f / l;

    for (int t = 0; t < TT; ++t) {
        float sc = 0.f;
        #pragma unroll
        for (int j = 0; j < FF; ++j) sc += qs[t][j] * kr[j];
        float a = expf(sc - m) * inv;
        g_attnh[(b * TT + t) * TT + s] = __float2half_rn(a);

        float v = a;
        #pragma unroll
        for (int off = 16; off > 0; off >>= 1)
            v += __shfl_down_sync(0xffffffffu, v, off);
        if (lane == 0) redp[wid][t] = v;
    }
    __syncthreads();
    if (s < TT)
        g_rs[b * TT + s] = redp[0][s] + redp[1][s] + redp[2][s] + redp[3][s];
}

// =============================================================================
// K3: y = attn @ x1 via HMMA. CTA = one batch x one 128-wide d tile.
// A = attnh [t][s] fp16 (cp.async, swizzled); B = x1 slice [s][d] converted
// fp32->fp16 inline; B frags via ldmatrix.trans. 256 thr = 8 warps (2m x 4n),
// warp tile 64t x 32d, 8 k-steps. Output stored fp16 to g_yh.
// Smem rows 256B, chunk swizzle c ^= (row & 7).
// =============================================================================
#define SMEM_KY 65536

__global__ __launch_bounds__(256) void k_y(const float* __restrict__ x1)
{
    extern __shared__ char smy[];
    const uint32_t sA = smem_u32(smy);            // attn tile 32 KB
    const uint32_t sX = sA + 32768;               // x1h tile 32 KB

    const int tid  = threadIdx.x;
    const int lane = tid & 31;
    const int wid  = tid >> 5;
    const int wm   = wid & 1;        // 2 warps in m (64 rows each)
    const int wn   = wid >> 1;       // 4 warps in n (32 cols each)
    const int dt   = blockIdx.x;     // 0..63
    const int b    = blockIdx.y;     // 0..15

    // attnh -> smem (16B chunks, swizzled)
    #pragma unroll
    for (int i = 0; i < 8; ++i) {
        int id = tid + i * 256;               // 0..2047
        int s = id >> 4, c = id & 15;
        cp_async16(sA + s * 256 + ((c ^ (s & 7)) << 4),
                   g_attnh + (size_t)(b * TT + s) * TT + c * 8);
    }
    CP_COMMIT();

    // x1 fp32 -> fp16 smem (swizzled)
    #pragma unroll
    for (int i = 0; i < 16; ++i) {
        int id = tid + i * 256;               // 0..4095
        int s = id >> 5, q = id & 31;
        float4 v = *(const float4*)&x1[(size_t)(b * TT + s) * DD + dt * 128 + q * 4];
        __half2 p0, p1;
        p0.x = __float2half_rn(v.x); p0.y = __float2half_rn(v.y);
        p1.x = __float2half_rn(v.z); p1.y = __float2half_rn(v.w);
        uint2 u; u.x = *(uint32_t*)&p0; u.y = *(uint32_t*)&p1;
        int c = q >> 1, h = q & 1;
        *(uint2*)(smy + 32768 + s * 256 + ((c ^ (s & 7)) << 4) + h * 8) = u;
    }
    CP_WAIT0();
    __syncthreads();

    float acc[4][4][4];
    #pragma unroll
    for (int a = 0; a < 4; ++a)
        #pragma unroll
        for (int bq = 0; bq < 4; ++bq)
            #pragma unroll
            for (int c = 0; c < 4; ++c) acc[a][bq][c] = 0.f;

    const int r_lane = (lane & 7) + ((lane >> 3) & 1) * 8;
    const int c_lane = lane >> 4;             // 0 or 1

    #pragma unroll
    for (int s16 = 0; s16 < 8; ++s16) {
        uint32_t af[4][4];
        #pragma unroll
        for (int mf = 0; mf < 4; ++mf) {
            int t = wm * 64 + mf * 16 + r_lane;
            int c = s16 * 2 + c_lane;
            ldsm4(af[mf], sA + t * 256 + ((c ^ (t & 7)) << 4));
        }
        #pragma unroll
        for (int nf2 = 0; nf2 < 2; ++nf2) {
            int srow = s16 * 16 + r_lane;
            int c = wn * 4 + nf2 * 2 + c_lane;
            uint32_t bt[4];
            ldsm4t(bt, sX + srow * 256 + ((c ^ (srow & 7)) << 4));
            #pragma unroll
            for (int mf = 0; mf < 4; ++mf) {
                mma16816h(acc[mf][nf2 * 2 + 0], af[mf], bt[0], bt[1]);
                mma16816h(acc[mf][nf2 * 2 + 1], af[mf], bt[2], bt[3]);
            }
        }
    }

    // store yh
    const int r_ep  = lane >> 2;
    const int cpair = (lane & 3) * 2;
    #pragma unroll
    for (int mf = 0; mf < 4; ++mf) {
        #pragma unroll
        for (int nf = 0; nf < 4; ++nf) {
            int t = wm * 64 + mf * 16 + r_ep;
            int d = dt * 128 + wn * 32 + nf * 8 + cpair;
            __half2 h0, h1;
            h0.x = __float2half_rn(acc[mf][nf][0]);
            h0.y = __float2half_rn(acc[mf][nf][1]);
            h1.x = __float2half_rn(acc[mf][nf][2]);
            h1.y = __float2half_rn(acc[mf][nf][3]);
            *(__half2*)&g_yh[(size_t)(b * TT + t) * DD + d]       = h0;
            *(__half2*)&g_yh[(size_t)(b * TT + t + 8) * DD + d]   = h1;
        }
    }
}

// =============================================================================
// K_split_w3: fp32 [G][D] -> fp16 row-major (streaming)
// =============================================================================
__global__ __launch_bounds__(256) void k_split_w3(const float* __restrict__ src)
{
    size_t i4 = ((size_t)blockIdx.x * 256 + threadIdx.x);
    float4 v = *(const float4*)&src[i4 * 4];
    __half2 h0; h0.x = __float2half_rn(v.x); h0.y = __float2half_rn(v.y);
    __half2 h1; h1.x = __float2half_rn(v.z); h1.y = __float2half_rn(v.w);
    uint2 hu;
    hu.x = *(uint32_t*)&h0; hu.y = *(uint32_t*)&h1;
    *(uint2*)&g_w3h[i4 * 4] = hu;
}

// =============================================================================
// K4: out[m,g] = sum_k y[m,k] w3[g,k] + rs[m] b3[g]  (unchanged from R9)
// =============================================================================
#define STAGE_BYTES 24576
#define NSTG 4
#define SMEM_K4 (NSTG * STAGE_BYTES)
#define OFF_B 16384

__global__ __launch_bounds__(512) void k_out_tc(
    const float* __restrict__ b3, float* __restrict__ out)
{
    extern __shared__ char smem[];
    const uint32_t sb = smem_u32(smem);
    const int tid  = threadIdx.x;
    const int lane = tid & 31;
    const int wid  = tid >> 5;
    const int wm   = wid & 3;
    const int wn   = wid >> 2;
    const int rb   = blockIdx.x;
    const int nb   = blockIdx.y;

    const __half* aP = g_yh  + (size_t)rb * 256 * DD;
    const __half* bP = g_w3h + (size_t)nb * 128 * DD;

    auto issue_stage = [&](int kt, int stage) {
        const uint32_t sbase = sb + stage * STAGE_BYTES;
        #pragma unroll
        for (int i = 0; i < 2; ++i) {
            const int id = i * 512 + tid;
            const int r  = id >> 2;
            const int c  = id & 3;
            uint32_t dst = sbase + r * 64 + ((c ^ ((r >> 1) & 3)) << 4);
            cp_async16(dst, aP + (size_t)r * DD + kt * 32 + c * 8);
        }
        {
            const int r = tid >> 2;
            const int c = tid & 3;
            uint32_t dst = sbase + OFF_B + r * 64 + ((c ^ ((r >> 1) & 3)) << 4);
            cp_async16(dst, bP + (size_t)r * DD + kt * 32 + c * 8);
        }
    };

    float acc[4][4][4];
    #pragma unroll
    for (int a = 0; a < 4; ++a)
        #pragma unroll
        for (int b2 = 0; b2 < 4; ++b2)
            #pragma unroll
            for (int c = 0; c < 4; ++c) acc[a][b2][c] = 0.f;

    const int r_lane = (lane & 7) + ((lane >> 3) & 1) * 8;
    const int c_lane = lane >> 4;

    int rA64[4], rAx[4], rB64[2], rBx[2];
    #pragma unroll
    for (int f = 0; f < 4; ++f) {
        int ra = wm * 64 + f * 16 + r_lane;
        rA64[f] = ra * 64; rAx[f] = (ra >> 1) & 3;
    }
    #pragma unroll
    for (int f = 0; f < 2; ++f) {
        int rn = wn * 32 + f * 16 + r_lane;
        rB64[f] = rn * 64; rBx[f] = (rn >> 1) & 3;
    }

    issue_stage(0, 0); CP_COMMIT();
    issue_stage(1, 1); CP_COMMIT();
    issue_stage(2, 2); CP_COMMIT();

    const int KT = DD / 32;
    for (int kt = 0; kt < KT; ++kt) {
        CP_WAIT2();
        __syncthreads();

        const uint32_t sbase = sb + (kt & (NSTG - 1)) * STAGE_BYTES;
        #pragma unroll
        for (int ks = 0; ks < 2; ++ks) {
            const int cbase = 2 * ks + c_lane;
            uint32_t af[4][4];
            #pragma unroll
            for (int mf = 0; mf < 4; ++mf)
                ldsm4(af[mf], sbase + rA64[mf] + ((cbase ^ rAx[mf]) << 4));
            #pragma unroll
            for (int nf2 = 0; nf2 < 2; ++nf2) {
                uint32_t bf[4];
                ldsm4(bf, sbase + OFF_B + rB64[nf2] + ((cbase ^ rBx[nf2]) << 4));
                #pragma unroll
                for (int mf = 0; mf < 4; ++mf) {
                    #pragma unroll
                    for (int s = 0; s < 2; ++s)
                        mma16816h(acc[mf][nf2 * 2 + s], af[mf], bf[s], bf[s + 2]);
                }
            }
        }
        __syncthreads();
        if (kt + 3 < KT) { issue_stage(kt + 3, (kt + 3) & (NSTG - 1)); }
        CP_COMMIT();
    }

    const int r_ep  = lane >> 2;
    const int cpair = (lane & 3) * 2;

    float rsv[4][2];
    #pragma unroll
    for (int mf = 0; mf < 4; ++mf) {
        int row = rb * 256 + wm * 64 + mf * 16 + r_ep;
        rsv[mf][0] = g_rs[row];
        rsv[mf][1] = g_rs[row + 8];
    }
    float b3v[4][2];
    #pragma unroll
    for (int nf = 0; nf < 4; ++nf) {
        int colg = nb * 128 + wn * 32 + nf * 8 + cpair;
        b3v[nf][0] = b3[colg];
        b3v[nf][1] = b3[colg + 1];
    }

    #pragma unroll
    for (int mf = 0; mf < 4; ++mf) {
        #pragma unroll
        for (int nf = 0; nf < 4; ++nf) {
            int row  = rb * 256 + wm * 64 + mf * 16 + r_ep;
            int colg = nb * 128 + wn * 32 + nf * 8 + cpair;
            float2 v0, v1;
            v0.x = acc[mf][nf][0] + rsv[mf][0] * b3v[nf][0];
            v0.y = acc[mf][nf][1] + rsv[mf][0] * b3v[nf][1];
            v1.x = acc[mf][nf][2] + rsv[mf][1] * b3v[nf][0];
            v1.y = acc[mf][nf][3] + rsv[mf][1] * b3v[nf][1];
            *(float2*)&out[(size_t)row * GG + colg]       = v0;
            *(float2*)&out[(size_t)(row + 8) * GG + colg] = v1;
        }
    }
}

// =============================================================================
extern "C" void kernel_launch(void* const* d_in, const int* in_sizes, int n_in,
                              void* d_out, int out_size)
{
    const float* x1 = (const float*)d_in[0];
    const float* x2 = (const float*)d_in[1];
    const float* w1 = (const float*)d_in[2];
    const float* b1 = (const float*)d_in[3];
    const float* w2 = (const float*)d_in[4];
    const float* b2 = (const float*)d_in[5];
    const float* w3 = (const float*)d_in[6];
    const float* b3 = (const float*)d_in[7];
    float* out = (float*)d_out;

    cudaFuncSetAttribute(k_out_tc, cudaFuncAttributeMaxDynamicSharedMemorySize, SMEM_K4);
    cudaFuncSetAttribute(k_y, cudaFuncAttributeMaxDynamicSharedMemorySize, SMEM_KY);

    k_split_w3<<<(size_t)GG * DD / (256 * 4), 256>>>(w3);
    k_qk<<<MM / 16, 256>>>(x1, x2, w1, b1, w2, b2);
    k_scores_softmax<<<BB, 128>>>();
    k_y<<<dim3(DD / 128, BB), 256, SMEM_KY>>>(x1);
    k_out_tc<<<dim3(MM / 256, GG / 128), 512, SMEM_K4>>>(b3, out);
}